// round 5
// baseline (speedup 1.0000x reference)
#include <cuda_runtime.h>
#include <cuda_bf16.h>
#include <math.h>
#include <stdint.h>

#define B_   2
#define S_   2048
#define E_   1024
#define H_   16
#define D_   64
#define MTOT (B_*S_)   // 4096
#define QSZ_ ((size_t)B_*H_*S_*D_)   // 4194304

// Scratch (allocation-free rule: __device__ globals)
// bf16 hi/lo buffers. x/W/attn: [row][hi1024|lo1024]. q/k/v: hi block then lo block, [B,H,S,D].
__device__ __align__(16) __nv_bfloat16 g_xb[(size_t)MTOT*2048];
__device__ __align__(16) __nv_bfloat16 g_wq[(size_t)E_*2048];
__device__ __align__(16) __nv_bfloat16 g_wk[(size_t)E_*2048];
__device__ __align__(16) __nv_bfloat16 g_wv[(size_t)E_*2048];
__device__ __align__(16) __nv_bfloat16 g_wo[(size_t)E_*2048];
__device__ __align__(16) __nv_bfloat16 g_ab[(size_t)MTOT*2048];
__device__ __align__(16) __nv_bfloat16 g_qb[2*QSZ_];
__device__ __align__(16) __nv_bfloat16 g_kb[2*QSZ_];
__device__ __align__(16) __nv_bfloat16 g_vb[2*QSZ_];

// ---------------------------------------------------------------------------
// PTX helpers (baseline PTX, compiles on plain compute_103)
// ---------------------------------------------------------------------------
__device__ __forceinline__ uint32_t smem_u32(const void* p) {
    uint32_t a;
    asm("{ .reg .u64 t; cvta.to.shared.u64 t, %1; cvt.u32.u64 %0, t; }"
        : "=r"(a) : "l"(p));
    return a;
}
__device__ __forceinline__ void ldsm_x4(uint32_t r[4], uint32_t addr) {
    asm volatile("ldmatrix.sync.aligned.m8n8.x4.shared.b16 {%0,%1,%2,%3}, [%4];"
        : "=r"(r[0]), "=r"(r[1]), "=r"(r[2]), "=r"(r[3]) : "r"(addr));
}
__device__ __forceinline__ void ldsm_x4_t(uint32_t r[4], uint32_t addr) {
    asm volatile("ldmatrix.sync.aligned.m8n8.x4.trans.shared.b16 {%0,%1,%2,%3}, [%4];"
        : "=r"(r[0]), "=r"(r[1]), "=r"(r[2]), "=r"(r[3]) : "r"(addr));
}
__device__ __forceinline__ void mma_bf16(float c[4], const uint32_t a[4],
                                         uint32_t b0, uint32_t b1) {
    asm volatile("mma.sync.aligned.m16n8k16.row.col.f32.bf16.bf16.f32 "
        "{%0,%1,%2,%3}, {%4,%5,%6,%7}, {%8,%9}, {%0,%1,%2,%3};"
        : "+f"(c[0]), "+f"(c[1]), "+f"(c[2]), "+f"(c[3])
        : "r"(a[0]), "r"(a[1]), "r"(a[2]), "r"(a[3]), "r"(b0), "r"(b1));
}
__device__ __forceinline__ uint32_t bf2_pack(float x, float y) {
    __nv_bfloat162 h = __floats2bfloat162_rn(x, y);
    return *reinterpret_cast<uint32_t*>(&h);
}
__device__ __forceinline__ void cp_async16(uint32_t dst, const void* src) {
    asm volatile("cp.async.cg.shared.global [%0], [%1], 16;"
        :: "r"(dst), "l"(src) : "memory");
}
#define CP_COMMIT() asm volatile("cp.async.commit_group;" ::: "memory")
#define CP_WAIT0()  asm volatile("cp.async.wait_group 0;" ::: "memory")
#define CP_WAIT1()  asm volatile("cp.async.wait_group 1;" ::: "memory")

// ---------------------------------------------------------------------------
// Pre-convert fp32 [nrows,1024] -> bf16 hi/lo [nrows,2048] ([hi1024|lo1024])
// ---------------------------------------------------------------------------
__global__ __launch_bounds__(256)
void convert_hl(const float* __restrict__ src, __nv_bfloat16* __restrict__ dst)
{
    int idx = blockIdx.x * 256 + threadIdx.x;    // float4 index, grid sized exactly
    int row = idx >> 8, c4 = idx & 255;
    float4 v = reinterpret_cast<const float4*>(src)[idx];
    float hx = __bfloat162float(__float2bfloat16_rn(v.x));
    float hy = __bfloat162float(__float2bfloat16_rn(v.y));
    float hz = __bfloat162float(__float2bfloat16_rn(v.z));
    float hw = __bfloat162float(__float2bfloat16_rn(v.w));
    uint2 hi = { bf2_pack(hx, hy), bf2_pack(hz, hw) };
    uint2 lo = { bf2_pack(v.x - hx, v.y - hy), bf2_pack(v.z - hz, v.w - hw) };
    *reinterpret_cast<uint2*>(&dst[(size_t)row * 2048 + c4 * 4])        = hi;
    *reinterpret_cast<uint2*>(&dst[(size_t)row * 2048 + 1024 + c4 * 4]) = lo;
}

// ---------------------------------------------------------------------------
// bf16x3 tensor-core GEMM, cp.async double-buffered:
//   C = (A * W^T + bias) [* scl]
// A: [M,2048] bf16 hi|lo.  W: [1024,2048] bf16 hi|lo.
// CTA tile 128x128, 256 threads (8 warps), warp tile 64x32 (4x4 m16n8k16).
// smem chunk: 128 rows x [hi32|lo32] bf16, stride 72. Double buffered.
// 3-term: hi*hi + hi*lo + lo*hi.
// LAYOUT 0: fp32 out C[m*1024+n]
// LAYOUT 1: bf16 hi/lo out scattered [B,H,S,D]; z=0 (Q) scaled by 1/8
// ---------------------------------------------------------------------------
#define SAST 72             // smem row stride in bf16 (144 bytes)
#define SAB  (128*SAST*2)   // bytes per operand buffer: 18432

template<int LAYOUT>
__global__ __launch_bounds__(256)
void hmma_gemm(const __nv_bfloat16* __restrict__ A,
               const __nv_bfloat16* __restrict__ W0,
               const __nv_bfloat16* __restrict__ W1,
               const __nv_bfloat16* __restrict__ W2,
               const float* __restrict__ b0p, const float* __restrict__ b1p,
               const float* __restrict__ b2p,
               void* __restrict__ C0v, void* __restrict__ C1v,
               void* __restrict__ C2v)
{
    extern __shared__ char smem[];
    const uint32_t base = smem_u32(smem);
    // sA0 @0, sA1 @18432, sB0 @36864, sB1 @55296; total 73728
    const int z = blockIdx.z;
    const __nv_bfloat16* W = (z == 0) ? W0 : (z == 1) ? W1 : W2;
    const float* bias      = (z == 0) ? b0p : (z == 1) ? b1p : b2p;
    void*        Cv        = (z == 0) ? C0v : (z == 1) ? C1v : C2v;
    const float  scl       = (LAYOUT == 1 && z == 0) ? 0.125f : 1.0f;

    const int t  = threadIdx.x;
    const int w  = t >> 5;
    const int l  = t & 31;
    const int wy = w >> 2;           // 0..1
    const int wx = w & 3;            // 0..3
    const int m0 = blockIdx.y * 128;
    const int n0 = blockIdx.x * 128;

    // per-thread cp.async addressing (8 transfers per operand per chunk)
    const int cp_row = t >> 1;             // 0..127
    const int cp_half = (t & 1) * 4;       // 0 or 4 (c8 base)

    float acc[4][4][4];
    #pragma unroll
    for (int i = 0; i < 4; i++)
        #pragma unroll
        for (int j = 0; j < 4; j++) {
            acc[i][j][0] = 0.f; acc[i][j][1] = 0.f;
            acc[i][j][2] = 0.f; acc[i][j][3] = 0.f;
        }

    const uint32_t a_row  = (uint32_t)(l & 15);
    const uint32_t a_koff = (l & 16) ? 8u : 0u;
    const uint32_t b_row  = (uint32_t)((l & 7) + ((l & 16) ? 8 : 0));
    const uint32_t b_koff = (l & 8) ? 8u : 0u;

    // issue one 32-elem K chunk into buffer sel
    auto issue = [&](int k0, int sel) {
        const uint32_t dA = base + sel * 18432;
        const uint32_t dB = base + 36864 + sel * 18432;
        const __nv_bfloat16* As = &A[(size_t)(m0 + cp_row) * 2048 + k0];
        const __nv_bfloat16* Ws = &W[(size_t)(n0 + cp_row) * 2048 + k0];
        const uint32_t drow = (uint32_t)(cp_row * SAST) * 2;
        #pragma unroll
        for (int j = 0; j < 4; j++) {
            int c8 = cp_half + j;
            int goff = c8 * 8 + ((c8 >= 4) ? 992 : 0);   // lo half lives at +1024-32
            cp_async16(dA + drow + (uint32_t)c8 * 16, As + goff);
            cp_async16(dB + drow + (uint32_t)c8 * 16, Ws + goff);
        }
        CP_COMMIT();
    };

    issue(0, 0);

    for (int kc = 0; kc < 32; kc++) {
        if (kc < 31) { issue((kc + 1) * 32, (kc + 1) & 1); CP_WAIT1(); }
        else         { CP_WAIT0(); }
        __syncthreads();

        const uint32_t sA = base + (kc & 1) * 18432;
        const uint32_t sB = base + 36864 + (kc & 1) * 18432;

        #pragma unroll
        for (int ka = 0; ka < 4; ka++) {
            uint32_t af[4][4];
            #pragma unroll
            for (int mi = 0; mi < 4; mi++) {
                uint32_t row = (uint32_t)(wy * 64 + mi * 16) + a_row;
                uint32_t col = (uint32_t)(ka * 16) + a_koff;
                ldsm_x4(af[mi], sA + row * (SAST * 2) + col * 2);
            }
            const int nkb  = (ka < 2) ? 2 : 1;
            const int kbl0 = (ka == 0) ? 0 : (ka == 1) ? 1 : (ka == 2) ? 0 : 1;
            const int kbl1 = (ka == 0) ? 2 : 3;
            #pragma unroll
            for (int j = 0; j < 2; j++) {
                if (j >= nkb) break;
                const int kb = (j == 0) ? kbl0 : kbl1;
                #pragma unroll
                for (int nb = 0; nb < 2; nb++) {
                    uint32_t bf[4];
                    uint32_t row = (uint32_t)(wx * 32 + nb * 16) + b_row;
                    uint32_t col = (uint32_t)(kb * 16) + b_koff;
                    ldsm_x4(bf, sB + row * (SAST * 2) + col * 2);
                    #pragma unroll
                    for (int mi = 0; mi < 4; mi++) {
                        mma_bf16(acc[mi][nb * 2 + 0], af[mi], bf[0], bf[1]);
                        mma_bf16(acc[mi][nb * 2 + 1], af[mi], bf[2], bf[3]);
                    }
                }
            }
        }
        __syncthreads();
    }

    // ---- epilogue
    #pragma unroll
    for (int mi = 0; mi < 4; mi++) {
        #pragma unroll
        for (int ni = 0; ni < 4; ni++) {
            int n = n0 + wx * 32 + ni * 8 + 2 * (l & 3);
            float2 bv = *reinterpret_cast<const float2*>(&bias[n]);
            #pragma unroll
            for (int half = 0; half < 2; half++) {
                int m = m0 + wy * 64 + mi * 16 + (l >> 2) + half * 8;
                float vx = acc[mi][ni][half * 2 + 0] + bv.x;
                float vy = acc[mi][ni][half * 2 + 1] + bv.y;
                if (LAYOUT == 0) {
                    float* C = (float*)Cv;
                    float2 ov; ov.x = vx; ov.y = vy;
                    *reinterpret_cast<float2*>(&C[(size_t)m * E_ + n]) = ov;
                } else {
                    vx *= scl; vy *= scl;
                    __nv_bfloat16* Cb = (__nv_bfloat16*)Cv;
                    float hx = __bfloat162float(__float2bfloat16_rn(vx));
                    float hy = __bfloat162float(__float2bfloat16_rn(vy));
                    uint32_t hi2 = bf2_pack(hx, hy);
                    uint32_t lo2 = bf2_pack(vx - hx, vy - hy);
                    int bb = m >> 11, s = m & 2047;
                    int hh = n >> 6,  d = n & 63;
                    size_t idx = ((((size_t)bb * H_ + hh) * S_ + s) << 6) + d;
                    *reinterpret_cast<uint32_t*>(&Cb[idx])        = hi2;
                    *reinterpret_cast<uint32_t*>(&Cb[QSZ_ + idx]) = lo2;
                }
            }
        }
    }
}

// ---------------------------------------------------------------------------
// Tensor-core flash attention (bf16x3), ALiBi + causal, cp.async double buffer
// grid = (S/64, H, B), block = 128 (4 warps). Warp = 16 query rows.
// smem per buffer: K tile 64 x [hi64|lo64] stride 136 (17408 B), same for V.
// Output written as bf16 hi/lo into g_ab [4096,2048].
// ---------------------------------------------------------------------------
#define KST 136
#define KBUF 17408            // 64*136*2 bytes

__global__ __launch_bounds__(128)
void flash_tc(__nv_bfloat16* __restrict__ outb)
{
    extern __shared__ char fsm[];
    const uint32_t base = smem_u32(fsm);
    // sK0 @0, sK1 @17408, sV0 @34816, sV1 @52224; total 69632

    const int t = threadIdx.x;
    const int w = t >> 5, l = t & 31;
    const int qt = blockIdx.x, h = blockIdx.y, b = blockIdx.z;
    const size_t hd_base = ((size_t)b * H_ + h) * S_ * D_;

    const float slope = exp2f(-0.5f * (float)(h + 1));   // H=16 power of 2

    // ---- stage Q tile into buffer 0 region, extract persistent A-fragments
    {
        __nv_bfloat16* sQ = reinterpret_cast<__nv_bfloat16*>(fsm);
        const uint4* qh4 = reinterpret_cast<const uint4*>(g_qb + hd_base + (size_t)qt * 64 * 64);
        const uint4* ql4 = reinterpret_cast<const uint4*>(g_qb + QSZ_ + hd_base + (size_t)qt * 64 * 64);
        #pragma unroll
        for (int i = 0; i < 4; i++) {
            int idx = t + i * 128;   // 0..511
            int row = idx >> 3, c8 = idx & 7;
            *reinterpret_cast<uint4*>(&sQ[row * KST + c8 * 8])      = qh4[idx];
            *reinterpret_cast<uint4*>(&sQ[row * KST + 64 + c8 * 8]) = ql4[idx];
        }
    }
    __syncthreads();

    uint32_t qhf[4][4], qlf[4][4];
    {
        uint32_t arow = (uint32_t)(w * 16 + (l & 15));
        uint32_t acol = (l & 16) ? 8u : 0u;
        #pragma unroll
        for (int kg = 0; kg < 4; kg++) {
            ldsm_x4(qhf[kg], base + (arow * KST + kg * 16 + acol) * 2);
            ldsm_x4(qlf[kg], base + (arow * KST + 64 + kg * 16 + acol) * 2);
        }
    }
    __syncthreads();

    // cp.async issue of one K/V tile pair into buffer sel
    auto issue = [&](int kt, int sel) {
        const __nv_bfloat16* kh = g_kb + hd_base + (size_t)kt * 64 * 64;
        const __nv_bfloat16* vh = g_vb + hd_base + (size_t)kt * 64 * 64;
        const uint32_t dK = base + sel * KBUF;
        const uint32_t dV = base + 2 * KBUF + sel * KBUF;
        #pragma unroll
        for (int i = 0; i < 4; i++) {
            int idx = t + i * 128;
            int row = idx >> 3, c8 = idx & 7;
            uint32_t soff = (uint32_t)(row * KST + c8 * 8) * 2;
            size_t goff = (size_t)row * 64 + c8 * 8;
            cp_async16(dK + soff,             kh + goff);
            cp_async16(dK + soff + 128,       kh + QSZ_ + goff);   // lo at col 64
            cp_async16(dV + soff,             vh + goff);
            cp_async16(dV + soff + 128,       vh + QSZ_ + goff);
        }
        CP_COMMIT();
    };

    const uint32_t brow  = (uint32_t)((l & 7) + ((l & 16) ? 8 : 0));
    const uint32_t bkoff = (l & 8) ? 8u : 0u;
    const uint32_t vrow  = (uint32_t)(l & 15);
    const uint32_t vcoff = (l & 16) ? 8u : 0u;

    const int qi0 = qt * 64 + w * 16 + (l >> 2);
    const int qi1 = qi0 + 8;
    const float rowb0 = slope * (float)qi0;
    const float rowb1 = slope * (float)qi1;

    float oacc[8][4];
    #pragma unroll
    for (int i = 0; i < 8; i++) {
        oacc[i][0] = 0.f; oacc[i][1] = 0.f; oacc[i][2] = 0.f; oacc[i][3] = 0.f;
    }
    float mst0 = -1e30f, mst1 = -1e30f, ls0 = 0.f, ls1 = 0.f;

    issue(0, 0);

    for (int kt = 0; kt <= qt; kt++) {
        if (kt < qt) { issue(kt + 1, (kt + 1) & 1); CP_WAIT1(); }
        else         { CP_WAIT0(); }
        __syncthreads();

        const int sel = kt & 1;
        const uint32_t sKa = base + sel * KBUF;
        const uint32_t sVa = base + 2 * KBUF + sel * KBUF;

        // ---- S = Q K^T (3-term: QhKh + QlKh + QhKl)
        float sacc[8][4];
        #pragma unroll
        for (int i = 0; i < 8; i++) {
            sacc[i][0] = 0.f; sacc[i][1] = 0.f; sacc[i][2] = 0.f; sacc[i][3] = 0.f;
        }
        #pragma unroll
        for (int kg = 0; kg < 4; kg++) {
            #pragma unroll
            for (int nb2 = 0; nb2 < 4; nb2++) {
                uint32_t bh[4], bl[4];
                ldsm_x4(bh, sKa + ((nb2 * 16 + brow) * KST + kg * 16 + bkoff) * 2);
                mma_bf16(sacc[2 * nb2],     qhf[kg], bh[0], bh[1]);
                mma_bf16(sacc[2 * nb2 + 1], qhf[kg], bh[2], bh[3]);
                mma_bf16(sacc[2 * nb2],     qlf[kg], bh[0], bh[1]);
                mma_bf16(sacc[2 * nb2 + 1], qlf[kg], bh[2], bh[3]);
                ldsm_x4(bl, sKa + ((nb2 * 16 + brow) * KST + 64 + kg * 16 + bkoff) * 2);
                mma_bf16(sacc[2 * nb2],     qhf[kg], bl[0], bl[1]);
                mma_bf16(sacc[2 * nb2 + 1], qhf[kg], bl[2], bl[3]);
            }
        }

        // ---- ALiBi bias + causal mask + online softmax
        const int kjb = kt * 64 + 2 * (l & 3);
        float rm0 = -1e30f, rm1 = -1e30f;
        #pragma unroll
        for (int nb = 0; nb < 8; nb++) {
            int kj0 = kjb + nb * 8;
            float f0 = slope * (float)kj0;
            float f1 = f0 + slope;
            float v00 = sacc[nb][0] + f0 - rowb0;
            float v01 = sacc[nb][1] + f1 - rowb0;
            float v10 = sacc[nb][2] + f0 - rowb1;
            float v11 = sacc[nb][3] + f1 - rowb1;
            if (kt == qt) {
                if (kj0     > qi0) v00 = -1e30f;
                if (kj0 + 1 > qi0) v01 = -1e30f;
                if (kj0     > qi1) v10 = -1e30f;
                if (kj0 + 1 > qi1) v11 = -1e30f;
            }
            sacc[nb][0] = v00; sacc[nb][1] = v01;
            sacc[nb][2] = v10; sacc[nb][3] = v11;
            rm0 = fmaxf(rm0, fmaxf(v00, v01));
            rm1 = fmaxf(rm1, fmaxf(v10, v11));
        }
        rm0 = fmaxf(rm0, __shfl_xor_sync(0xffffffffu, rm0, 1));
        rm0 = fmaxf(rm0, __shfl_xor_sync(0xffffffffu, rm0, 2));
        rm1 = fmaxf(rm1, __shfl_xor_sync(0xffffffffu, rm1, 1));
        rm1 = fmaxf(rm1, __shfl_xor_sync(0xffffffffu, rm1, 2));

        float mn0 = fmaxf(mst0, rm0), mn1 = fmaxf(mst1, rm1);
        float al0 = __expf(mst0 - mn0), al1 = __expf(mst1 - mn1);
        mst0 = mn0; mst1 = mn1;

        float rs0 = 0.f, rs1 = 0.f;
        #pragma unroll
        for (int nb = 0; nb < 8; nb++) {
            float p00 = __expf(sacc[nb][0] - mn0);
            float p01 = __expf(sacc[nb][1] - mn0);
            float p10 = __expf(sacc[nb][2] - mn1);
            float p11 = __expf(sacc[nb][3] - mn1);
            sacc[nb][0] = p00; sacc[nb][1] = p01;
            sacc[nb][2] = p10; sacc[nb][3] = p11;
            rs0 += p00 + p01;
            rs1 += p10 + p11;
        }
        rs0 += __shfl_xor_sync(0xffffffffu, rs0, 1);
        rs0 += __shfl_xor_sync(0xffffffffu, rs0, 2);
        rs1 += __shfl_xor_sync(0xffffffffu, rs1, 1);
        rs1 += __shfl_xor_sync(0xffffffffu, rs1, 2);
        ls0 = ls0 * al0 + rs0;
        ls1 = ls1 * al1 + rs1;

        #pragma unroll
        for (int nd = 0; nd < 8; nd++) {
            oacc[nd][0] *= al0; oacc[nd][1] *= al0;
            oacc[nd][2] *= al1; oacc[nd][3] *= al1;
        }

        // ---- O += P V (3-term: PhVh + PlVh + PhVl); P frags from S C-frags
        #pragma unroll
        for (int kg = 0; kg < 4; kg++) {
            float p00 = sacc[2 * kg][0],     p01 = sacc[2 * kg][1];
            float p10 = sacc[2 * kg][2],     p11 = sacc[2 * kg][3];
            float p20 = sacc[2 * kg + 1][0], p21 = sacc[2 * kg + 1][1];
            float p30 = sacc[2 * kg + 1][2], p31 = sacc[2 * kg + 1][3];
            float h00 = __bfloat162float(__float2bfloat16_rn(p00));
            float h01 = __bfloat162float(__float2bfloat16_rn(p01));
            float h10 = __bfloat162float(__float2bfloat16_rn(p10));
            float h11 = __bfloat162float(__float2bfloat16_rn(p11));
            float h20 = __bfloat162float(__float2bfloat16_rn(p20));
            float h21 = __bfloat162float(__float2bfloat16_rn(p21));
            float h30 = __bfloat162float(__float2bfloat16_rn(p30));
            float h31 = __bfloat162float(__float2bfloat16_rn(p31));
            uint32_t ah[4], alo[4];
            ah[0]  = bf2_pack(h00, h01);
            ah[1]  = bf2_pack(h10, h11);
            ah[2]  = bf2_pack(h20, h21);
            ah[3]  = bf2_pack(h30, h31);
            alo[0] = bf2_pack(p00 - h00, p01 - h01);
            alo[1] = bf2_pack(p10 - h10, p11 - h11);
            alo[2] = bf2_pack(p20 - h20, p21 - h21);
            alo[3] = bf2_pack(p30 - h30, p31 - h31);

            #pragma unroll
            for (int nd2 = 0; nd2 < 4; nd2++) {
                uint32_t vh[4], vl[4];
                ldsm_x4_t(vh, sVa + ((kg * 16 + vrow) * KST + nd2 * 16 + vcoff) * 2);
                mma_bf16(oacc[2 * nd2],     ah,  vh[0], vh[1]);
                mma_bf16(oacc[2 * nd2 + 1], ah,  vh[2], vh[3]);
                mma_bf16(oacc[2 * nd2],     alo, vh[0], vh[1]);
                mma_bf16(oacc[2 * nd2 + 1], alo, vh[2], vh[3]);
                ldsm_x4_t(vl, sVa + ((kg * 16 + vrow) * KST + 64 + nd2 * 16 + vcoff) * 2);
                mma_bf16(oacc[2 * nd2],     ah,  vl[0], vl[1]);
                mma_bf16(oacc[2 * nd2 + 1], ah,  vl[2], vl[3]);
            }
        }
        __syncthreads();
    }

    // ---- normalize + write bf16 hi/lo into g_ab [4096, 2048]
    const float inv0 = 1.f / ls0, inv1 = 1.f / ls1;
    const int row0 = qt * 64 + w * 16 + (l >> 2);
    const size_t rbase0 = ((size_t)b * S_ + row0) * 2048;
    const size_t rbase1 = ((size_t)b * S_ + row0 + 8) * 2048;
    #pragma unroll
    for (int nd = 0; nd < 8; nd++) {
        int col = h * 64 + nd * 8 + 2 * (l & 3);
        float o00 = oacc[nd][0] * inv0, o01 = oacc[nd][1] * inv0;
        float o10 = oacc[nd][2] * inv1, o11 = oacc[nd][3] * inv1;
        float h00 = __bfloat162float(__float2bfloat16_rn(o00));
        float h01 = __bfloat162float(__float2bfloat16_rn(o01));
        float h10 = __bfloat162float(__float2bfloat16_rn(o10));
        float h11 = __bfloat162float(__float2bfloat16_rn(o11));
        *reinterpret_cast<uint32_t*>(&outb[rbase0 + col])        = bf2_pack(h00, h01);
        *reinterpret_cast<uint32_t*>(&outb[rbase0 + 1024 + col]) = bf2_pack(o00 - h00, o01 - h01);
        *reinterpret_cast<uint32_t*>(&outb[rbase1 + col])        = bf2_pack(h10, h11);
        *reinterpret_cast<uint32_t*>(&outb[rbase1 + 1024 + col]) = bf2_pack(o10 - h10, o11 - h11);
    }
}

// ---------------------------------------------------------------------------
extern "C" void kernel_launch(void* const* d_in, const int* in_sizes, int n_in,
                              void* d_out, int out_size)
{
    const float* x  = (const float*)d_in[0];
    const float* Wq = (const float*)d_in[1];
    const float* bq = (const float*)d_in[2];
    const float* Wk = (const float*)d_in[3];
    const float* bk = (const float*)d_in[4];
    const float* Wv = (const float*)d_in[5];
    const float* bv = (const float*)d_in[6];
    const float* Wo = (const float*)d_in[7];
    const float* bo = (const float*)d_in[8];

    __nv_bfloat16 *xb, *wqb, *wkb, *wvb, *wob, *ab, *qp, *kp, *vp;
    cudaGetSymbolAddress((void**)&xb,  g_xb);
    cudaGetSymbolAddress((void**)&wqb, g_wq);
    cudaGetSymbolAddress((void**)&wkb, g_wk);
    cudaGetSymbolAddress((void**)&wvb, g_wv);
    cudaGetSymbolAddress((void**)&wob, g_wo);
    cudaGetSymbolAddress((void**)&ab,  g_ab);
    cudaGetSymbolAddress((void**)&qp,  g_qb);
    cudaGetSymbolAddress((void**)&kp,  g_kb);
    cudaGetSymbolAddress((void**)&vp,  g_vb);

    const int SMEM_GEMM = 4 * SAB;            // 73728 B
    cudaFuncSetAttribute(hmma_gemm<0>, cudaFuncAttributeMaxDynamicSharedMemorySize, SMEM_GEMM);
    cudaFuncSetAttribute(hmma_gemm<1>, cudaFuncAttributeMaxDynamicSharedMemorySize, SMEM_GEMM);
    const int SMEM_FLASH = 4 * KBUF;          // 69632 B
    cudaFuncSetAttribute(flash_tc, cudaFuncAttributeMaxDynamicSharedMemorySize, SMEM_FLASH);

    // pre-convert inputs to bf16 hi/lo
    convert_hl<<<MTOT, 256>>>(x, xb);          // 4096 rows -> 4096*256/256 blocks
    convert_hl<<<E_, 256>>>(Wq, wqb);
    convert_hl<<<E_, 256>>>(Wk, wkb);
    convert_hl<<<E_, 256>>>(Wv, wvb);
    convert_hl<<<E_, 256>>>(Wo, wob);

    // fused Q/K/V projections (bf16 hi/lo out, Q pre-scaled by 1/8)
    dim3 qkv_grid(E_ / 128, MTOT / 128, 3);
    hmma_gemm<1><<<qkv_grid, 256, SMEM_GEMM>>>(xb, wqb, wkb, wvb, bq, bk, bv, qp, kp, vp);

    // tensor-core flash attention (writes bf16 hi/lo attn output)
    dim3 fgrid(S_ / 64, H_, B_);
    flash_tc<<<fgrid, 128, SMEM_FLASH>>>(ab);

    // output projection (fp32 out)
    dim3 o_grid(E_ / 128, MTOT / 128, 1);
    hmma_gemm<0><<<o_grid, 256, SMEM_GEMM>>>(ab, wob, wob, wob, bo, bo, bo,
                                             d_out, d_out, d_out);
}

// round 6
// speedup vs baseline: 1.0923x; 1.0923x over previous
#include <cuda_runtime.h>
#include <cuda_bf16.h>
#include <math.h>
#include <stdint.h>

#define B_   2
#define S_   2048
#define E_   1024
#define H_   16
#define D_   64
#define MTOT (B_*S_)   // 4096
#define QSZ_ ((size_t)B_*H_*S_*D_)   // 4194304

// Scratch (allocation-free rule: __device__ globals)
// bf16 hi/lo buffers. x/W/attn: [row][hi1024|lo1024]. q/k/v: hi block then lo block, [B,H,S,D].
__device__ __align__(16) __nv_bfloat16 g_xb[(size_t)MTOT*2048];
__device__ __align__(16) __nv_bfloat16 g_wq[(size_t)E_*2048];
__device__ __align__(16) __nv_bfloat16 g_wk[(size_t)E_*2048];
__device__ __align__(16) __nv_bfloat16 g_wv[(size_t)E_*2048];
__device__ __align__(16) __nv_bfloat16 g_wo[(size_t)E_*2048];
__device__ __align__(16) __nv_bfloat16 g_ab[(size_t)MTOT*2048];
__device__ __align__(16) __nv_bfloat16 g_qb[2*QSZ_];
__device__ __align__(16) __nv_bfloat16 g_kb[2*QSZ_];
__device__ __align__(16) __nv_bfloat16 g_vb[2*QSZ_];

// ---------------------------------------------------------------------------
// PTX helpers (baseline PTX, compiles on plain compute_103)
// ---------------------------------------------------------------------------
__device__ __forceinline__ uint32_t smem_u32(const void* p) {
    uint32_t a;
    asm("{ .reg .u64 t; cvta.to.shared.u64 t, %1; cvt.u32.u64 %0, t; }"
        : "=r"(a) : "l"(p));
    return a;
}
__device__ __forceinline__ void ldsm_x4(uint32_t r[4], uint32_t addr) {
    asm volatile("ldmatrix.sync.aligned.m8n8.x4.shared.b16 {%0,%1,%2,%3}, [%4];"
        : "=r"(r[0]), "=r"(r[1]), "=r"(r[2]), "=r"(r[3]) : "r"(addr));
}
__device__ __forceinline__ void ldsm_x4_t(uint32_t r[4], uint32_t addr) {
    asm volatile("ldmatrix.sync.aligned.m8n8.x4.trans.shared.b16 {%0,%1,%2,%3}, [%4];"
        : "=r"(r[0]), "=r"(r[1]), "=r"(r[2]), "=r"(r[3]) : "r"(addr));
}
__device__ __forceinline__ void mma_bf16(float c[4], const uint32_t a[4],
                                         uint32_t b0, uint32_t b1) {
    asm volatile("mma.sync.aligned.m16n8k16.row.col.f32.bf16.bf16.f32 "
        "{%0,%1,%2,%3}, {%4,%5,%6,%7}, {%8,%9}, {%0,%1,%2,%3};"
        : "+f"(c[0]), "+f"(c[1]), "+f"(c[2]), "+f"(c[3])
        : "r"(a[0]), "r"(a[1]), "r"(a[2]), "r"(a[3]), "r"(b0), "r"(b1));
}
__device__ __forceinline__ uint32_t bf2_pack(float x, float y) {
    __nv_bfloat162 h = __floats2bfloat162_rn(x, y);
    return *reinterpret_cast<uint32_t*>(&h);
}

// ---------------------------------------------------------------------------
// Pre-convert fp32 [nrows,1024] -> bf16 hi/lo [nrows,2048] ([hi1024|lo1024])
// ---------------------------------------------------------------------------
__global__ __launch_bounds__(256)
void convert_hl(const float* __restrict__ src, __nv_bfloat16* __restrict__ dst)
{
    int idx = blockIdx.x * 256 + threadIdx.x;    // float4 index
    int row = idx >> 8, c4 = idx & 255;
    float4 v = reinterpret_cast<const float4*>(src)[idx];
    float hx = __bfloat162float(__float2bfloat16_rn(v.x));
    float hy = __bfloat162float(__float2bfloat16_rn(v.y));
    float hz = __bfloat162float(__float2bfloat16_rn(v.z));
    float hw = __bfloat162float(__float2bfloat16_rn(v.w));
    uint2 hi = { bf2_pack(hx, hy), bf2_pack(hz, hw) };
    uint2 lo = { bf2_pack(v.x - hx, v.y - hy), bf2_pack(v.z - hz, v.w - hw) };
    *reinterpret_cast<uint2*>(&dst[(size_t)row * 2048 + c4 * 4])        = hi;
    *reinterpret_cast<uint2*>(&dst[(size_t)row * 2048 + 1024 + c4 * 4]) = lo;
}

// ---------------------------------------------------------------------------
// bf16x3 tensor-core GEMM (R4 loop structure, pre-converted bf16 inputs):
//   C = (A * W^T + bias) [* scl]
// A: [M,2048] bf16 hi|lo.  W: [1024,2048] bf16 hi|lo.
// CTA tile 128x128, 256 threads (8 warps), warp tile 64x32 (4x4 m16n8k16).
// smem chunk: 128 rows x [hi32|lo32] bf16, stride 72.
// 3-term: hi*hi + hi*lo + lo*hi.
// LAYOUT 0: fp32 out C[m*1024+n]
// LAYOUT 1: bf16 hi/lo out scattered [B,H,S,D]; z=0 (Q) scaled by 1/8
// ---------------------------------------------------------------------------
#define SAST 72             // smem row stride in bf16 (144 bytes)
#define SAB  (128*SAST*2)   // bytes per operand tile: 18432

template<int LAYOUT>
__global__ __launch_bounds__(256)
void hmma_gemm(const __nv_bfloat16* __restrict__ A,
               const __nv_bfloat16* __restrict__ W0,
               const __nv_bfloat16* __restrict__ W1,
               const __nv_bfloat16* __restrict__ W2,
               const float* __restrict__ b0p, const float* __restrict__ b1p,
               const float* __restrict__ b2p,
               void* __restrict__ C0v, void* __restrict__ C1v,
               void* __restrict__ C2v)
{
    extern __shared__ char smem[];
    __nv_bfloat16* sAp = reinterpret_cast<__nv_bfloat16*>(smem);
    __nv_bfloat16* sBp = reinterpret_cast<__nv_bfloat16*>(smem + SAB);
    const uint32_t sA = smem_u32(sAp);
    const uint32_t sB = smem_u32(sBp);

    const int z = blockIdx.z;
    const __nv_bfloat16* W = (z == 0) ? W0 : (z == 1) ? W1 : W2;
    const float* bias      = (z == 0) ? b0p : (z == 1) ? b1p : b2p;
    void*        Cv        = (z == 0) ? C0v : (z == 1) ? C1v : C2v;
    const float  scl       = (LAYOUT == 1 && z == 0) ? 0.125f : 1.0f;

    const int t  = threadIdx.x;
    const int w  = t >> 5;
    const int l  = t & 31;
    const int wy = w >> 2;           // 0..1
    const int wx = w & 3;            // 0..3
    const int m0 = blockIdx.y * 128;
    const int n0 = blockIdx.x * 128;

    float acc[4][4][4];
    #pragma unroll
    for (int i = 0; i < 4; i++)
        #pragma unroll
        for (int j = 0; j < 4; j++) {
            acc[i][j][0] = 0.f; acc[i][j][1] = 0.f;
            acc[i][j][2] = 0.f; acc[i][j][3] = 0.f;
        }

    const uint32_t a_row  = (uint32_t)(l & 15);
    const uint32_t a_koff = (l & 16) ? 8u : 0u;
    const uint32_t b_row  = (uint32_t)((l & 7) + ((l & 16) ? 8 : 0));
    const uint32_t b_koff = (l & 8) ? 8u : 0u;

    // per-thread load/store indexing: 1024 uint4 per operand per chunk
    // idx = t + i*256; row = idx>>3 (0..127); c8 = idx&7
    // gmem col offset: c8*8 + (c8>=4 ? 992 : 0)  (lo half at +1024-32)
    for (int k0 = 0; k0 < 1024; k0 += 32) {
        uint4 va[4], vb[4];
        #pragma unroll
        for (int i = 0; i < 4; i++) {
            int idx = t + i * 256;
            int row = idx >> 3, c8 = idx & 7;
            int goff = k0 + c8 * 8 + ((c8 >= 4) ? 992 : 0);
            va[i] = *reinterpret_cast<const uint4*>(&A[(size_t)(m0 + row) * 2048 + goff]);
            vb[i] = *reinterpret_cast<const uint4*>(&W[(size_t)(n0 + row) * 2048 + goff]);
        }
        __syncthreads();   // previous chunk fully consumed

        #pragma unroll
        for (int i = 0; i < 4; i++) {
            int idx = t + i * 256;
            int row = idx >> 3, c8 = idx & 7;
            *reinterpret_cast<uint4*>(&sAp[row * SAST + c8 * 8]) = va[i];
            *reinterpret_cast<uint4*>(&sBp[row * SAST + c8 * 8]) = vb[i];
        }
        __syncthreads();

        #pragma unroll
        for (int ka = 0; ka < 4; ka++) {
            uint32_t af[4][4];
            #pragma unroll
            for (int mi = 0; mi < 4; mi++) {
                uint32_t row = (uint32_t)(wy * 64 + mi * 16) + a_row;
                uint32_t col = (uint32_t)(ka * 16) + a_koff;
                ldsm_x4(af[mi], sA + row * (SAST * 2) + col * 2);
            }
            const int nkb  = (ka < 2) ? 2 : 1;
            const int kbl0 = (ka == 0) ? 0 : (ka == 1) ? 1 : (ka == 2) ? 0 : 1;
            const int kbl1 = (ka == 0) ? 2 : 3;
            #pragma unroll
            for (int j = 0; j < 2; j++) {
                if (j >= nkb) break;
                const int kb = (j == 0) ? kbl0 : kbl1;
                #pragma unroll
                for (int nb = 0; nb < 2; nb++) {
                    uint32_t bf[4];
                    uint32_t row = (uint32_t)(wx * 32 + nb * 16) + b_row;
                    uint32_t col = (uint32_t)(kb * 16) + b_koff;
                    ldsm_x4(bf, sB + row * (SAST * 2) + col * 2);
                    #pragma unroll
                    for (int mi = 0; mi < 4; mi++) {
                        mma_bf16(acc[mi][nb * 2 + 0], af[mi], bf[0], bf[1]);
                        mma_bf16(acc[mi][nb * 2 + 1], af[mi], bf[2], bf[3]);
                    }
                }
            }
        }
    }

    // ---- epilogue
    #pragma unroll
    for (int mi = 0; mi < 4; mi++) {
        #pragma unroll
        for (int ni = 0; ni < 4; ni++) {
            int n = n0 + wx * 32 + ni * 8 + 2 * (l & 3);
            float2 bv = *reinterpret_cast<const float2*>(&bias[n]);
            #pragma unroll
            for (int half = 0; half < 2; half++) {
                int m = m0 + wy * 64 + mi * 16 + (l >> 2) + half * 8;
                float vx = acc[mi][ni][half * 2 + 0] + bv.x;
                float vy = acc[mi][ni][half * 2 + 1] + bv.y;
                if (LAYOUT == 0) {
                    float* C = (float*)Cv;
                    float2 ov; ov.x = vx; ov.y = vy;
                    *reinterpret_cast<float2*>(&C[(size_t)m * E_ + n]) = ov;
                } else {
                    vx *= scl; vy *= scl;
                    __nv_bfloat16* Cb = (__nv_bfloat16*)Cv;
                    float hx = __bfloat162float(__float2bfloat16_rn(vx));
                    float hy = __bfloat162float(__float2bfloat16_rn(vy));
                    uint32_t hi2 = bf2_pack(hx, hy);
                    uint32_t lo2 = bf2_pack(vx - hx, vy - hy);
                    int bb = m >> 11, s = m & 2047;
                    int hh = n >> 6,  d = n & 63;
                    size_t idx = ((((size_t)bb * H_ + hh) * S_ + s) << 6) + d;
                    *reinterpret_cast<uint32_t*>(&Cb[idx])        = hi2;
                    *reinterpret_cast<uint32_t*>(&Cb[QSZ_ + idx]) = lo2;
                }
            }
        }
    }
}

// ---------------------------------------------------------------------------
// Tensor-core flash attention (bf16x3), ALiBi + causal (R4 structure)
// grid = (S/64, H, B), block = 128 (4 warps). Warp = 16 query rows.
// smem rows: [hi(64) | lo(64)] bf16, stride 136.
// Output: bf16 hi/lo into g_ab [4096, 2048].
// ---------------------------------------------------------------------------
#define KST 136

__global__ __launch_bounds__(128)
void flash_tc(__nv_bfloat16* __restrict__ outb)
{
    __shared__ __align__(16) __nv_bfloat16 sK[64 * KST];
    __shared__ __align__(16) __nv_bfloat16 sV[64 * KST];

    const int t = threadIdx.x;
    const int w = t >> 5, l = t & 31;
    const int qt = blockIdx.x, h = blockIdx.y, b = blockIdx.z;
    const size_t hd_base = ((size_t)b * H_ + h) * S_ * D_;

    const uint32_t sKa = smem_u32(sK);
    const uint32_t sVa = smem_u32(sV);

    const float slope = exp2f(-0.5f * (float)(h + 1));   // H=16 power of 2

    // ---- stage Q tile into sK, extract persistent A-fragments
    {
        const uint4* qh4 = reinterpret_cast<const uint4*>(g_qb + hd_base + (size_t)qt * 64 * 64);
        const uint4* ql4 = reinterpret_cast<const uint4*>(g_qb + QSZ_ + hd_base + (size_t)qt * 64 * 64);
        #pragma unroll
        for (int i = 0; i < 4; i++) {
            int idx = t + i * 128;   // 0..511
            int row = idx >> 3, c8 = idx & 7;
            *reinterpret_cast<uint4*>(&sK[row * KST + c8 * 8])      = qh4[idx];
            *reinterpret_cast<uint4*>(&sK[row * KST + 64 + c8 * 8]) = ql4[idx];
        }
    }
    __syncthreads();

    uint32_t qhf[4][4], qlf[4][4];
    {
        uint32_t arow = (uint32_t)(w * 16 + (l & 15));
        uint32_t acol = (l & 16) ? 8u : 0u;
        #pragma unroll
        for (int kg = 0; kg < 4; kg++) {
            ldsm_x4(qhf[kg], sKa + (arow * KST + kg * 16 + acol) * 2);
            ldsm_x4(qlf[kg], sKa + (arow * KST + 64 + kg * 16 + acol) * 2);
        }
    }
    __syncthreads();

    const uint32_t brow  = (uint32_t)((l & 7) + ((l & 16) ? 8 : 0));
    const uint32_t bkoff = (l & 8) ? 8u : 0u;
    const uint32_t vrow  = (uint32_t)(l & 15);
    const uint32_t vcoff = (l & 16) ? 8u : 0u;

    const int qi0 = qt * 64 + w * 16 + (l >> 2);
    const int qi1 = qi0 + 8;
    const float rowb0 = slope * (float)qi0;
    const float rowb1 = slope * (float)qi1;

    float oacc[8][4];
    #pragma unroll
    for (int i = 0; i < 8; i++) {
        oacc[i][0] = 0.f; oacc[i][1] = 0.f; oacc[i][2] = 0.f; oacc[i][3] = 0.f;
    }
    float mst0 = -1e30f, mst1 = -1e30f, ls0 = 0.f, ls1 = 0.f;

    for (int kt = 0; kt <= qt; kt++) {
        // ---- load K/V bf16 tiles (hi|lo)
        {
            const uint4* kh4 = reinterpret_cast<const uint4*>(g_kb + hd_base + (size_t)kt * 64 * 64);
            const uint4* kl4 = reinterpret_cast<const uint4*>(g_kb + QSZ_ + hd_base + (size_t)kt * 64 * 64);
            const uint4* vh4 = reinterpret_cast<const uint4*>(g_vb + hd_base + (size_t)kt * 64 * 64);
            const uint4* vl4 = reinterpret_cast<const uint4*>(g_vb + QSZ_ + hd_base + (size_t)kt * 64 * 64);
            #pragma unroll
            for (int i = 0; i < 4; i++) {
                int idx = t + i * 128;
                int row = idx >> 3, c8 = idx & 7;
                *reinterpret_cast<uint4*>(&sK[row * KST + c8 * 8])      = kh4[idx];
                *reinterpret_cast<uint4*>(&sK[row * KST + 64 + c8 * 8]) = kl4[idx];
                *reinterpret_cast<uint4*>(&sV[row * KST + c8 * 8])      = vh4[idx];
                *reinterpret_cast<uint4*>(&sV[row * KST + 64 + c8 * 8]) = vl4[idx];
            }
        }
        __syncthreads();

        // ---- S = Q K^T (3-term: QhKh + QlKh + QhKl)
        float sacc[8][4];
        #pragma unroll
        for (int i = 0; i < 8; i++) {
            sacc[i][0] = 0.f; sacc[i][1] = 0.f; sacc[i][2] = 0.f; sacc[i][3] = 0.f;
        }
        #pragma unroll
        for (int kg = 0; kg < 4; kg++) {
            #pragma unroll
            for (int nb2 = 0; nb2 < 4; nb2++) {
                uint32_t bh[4], bl[4];
                ldsm_x4(bh, sKa + ((nb2 * 16 + brow) * KST + kg * 16 + bkoff) * 2);
                mma_bf16(sacc[2 * nb2],     qhf[kg], bh[0], bh[1]);
                mma_bf16(sacc[2 * nb2 + 1], qhf[kg], bh[2], bh[3]);
                mma_bf16(sacc[2 * nb2],     qlf[kg], bh[0], bh[1]);
                mma_bf16(sacc[2 * nb2 + 1], qlf[kg], bh[2], bh[3]);
                ldsm_x4(bl, sKa + ((nb2 * 16 + brow) * KST + 64 + kg * 16 + bkoff) * 2);
                mma_bf16(sacc[2 * nb2],     qhf[kg], bl[0], bl[1]);
                mma_bf16(sacc[2 * nb2 + 1], qhf[kg], bl[2], bl[3]);
            }
        }

        // ---- ALiBi bias + causal mask + online softmax
        const int kjb = kt * 64 + 2 * (l & 3);
        float rm0 = -1e30f, rm1 = -1e30f;
        #pragma unroll
        for (int nb = 0; nb < 8; nb++) {
            int kj0 = kjb + nb * 8;
            float f0 = slope * (float)kj0;
            float f1 = f0 + slope;
            float v00 = sacc[nb][0] + f0 - rowb0;
            float v01 = sacc[nb][1] + f1 - rowb0;
            float v10 = sacc[nb][2] + f0 - rowb1;
            float v11 = sacc[nb][3] + f1 - rowb1;
            if (kt == qt) {
                if (kj0     > qi0) v00 = -1e30f;
                if (kj0 + 1 > qi0) v01 = -1e30f;
                if (kj0     > qi1) v10 = -1e30f;
                if (kj0 + 1 > qi1) v11 = -1e30f;
            }
            sacc[nb][0] = v00; sacc[nb][1] = v01;
            sacc[nb][2] = v10; sacc[nb][3] = v11;
            rm0 = fmaxf(rm0, fmaxf(v00, v01));
            rm1 = fmaxf(rm1, fmaxf(v10, v11));
        }
        rm0 = fmaxf(rm0, __shfl_xor_sync(0xffffffffu, rm0, 1));
        rm0 = fmaxf(rm0, __shfl_xor_sync(0xffffffffu, rm0, 2));
        rm1 = fmaxf(rm1, __shfl_xor_sync(0xffffffffu, rm1, 1));
        rm1 = fmaxf(rm1, __shfl_xor_sync(0xffffffffu, rm1, 2));

        float mn0 = fmaxf(mst0, rm0), mn1 = fmaxf(mst1, rm1);
        float al0 = __expf(mst0 - mn0), al1 = __expf(mst1 - mn1);
        mst0 = mn0; mst1 = mn1;

        float rs0 = 0.f, rs1 = 0.f;
        #pragma unroll
        for (int nb = 0; nb < 8; nb++) {
            float p00 = __expf(sacc[nb][0] - mn0);
            float p01 = __expf(sacc[nb][1] - mn0);
            float p10 = __expf(sacc[nb][2] - mn1);
            float p11 = __expf(sacc[nb][3] - mn1);
            sacc[nb][0] = p00; sacc[nb][1] = p01;
            sacc[nb][2] = p10; sacc[nb][3] = p11;
            rs0 += p00 + p01;
            rs1 += p10 + p11;
        }
        rs0 += __shfl_xor_sync(0xffffffffu, rs0, 1);
        rs0 += __shfl_xor_sync(0xffffffffu, rs0, 2);
        rs1 += __shfl_xor_sync(0xffffffffu, rs1, 1);
        rs1 += __shfl_xor_sync(0xffffffffu, rs1, 2);
        ls0 = ls0 * al0 + rs0;
        ls1 = ls1 * al1 + rs1;

        #pragma unroll
        for (int nd = 0; nd < 8; nd++) {
            oacc[nd][0] *= al0; oacc[nd][1] *= al0;
            oacc[nd][2] *= al1; oacc[nd][3] *= al1;
        }

        // ---- O += P V (3-term: PhVh + PlVh + PhVl); P frags from S C-frags
        #pragma unroll
        for (int kg = 0; kg < 4; kg++) {
            float p00 = sacc[2 * kg][0],     p01 = sacc[2 * kg][1];
            float p10 = sacc[2 * kg][2],     p11 = sacc[2 * kg][3];
            float p20 = sacc[2 * kg + 1][0], p21 = sacc[2 * kg + 1][1];
            float p30 = sacc[2 * kg + 1][2], p31 = sacc[2 * kg + 1][3];
            float h00 = __bfloat162float(__float2bfloat16_rn(p00));
            float h01 = __bfloat162float(__float2bfloat16_rn(p01));
            float h10 = __bfloat162float(__float2bfloat16_rn(p10));
            float h11 = __bfloat162float(__float2bfloat16_rn(p11));
            float h20 = __bfloat162float(__float2bfloat16_rn(p20));
            float h21 = __bfloat162float(__float2bfloat16_rn(p21));
            float h30 = __bfloat162float(__float2bfloat16_rn(p30));
            float h31 = __bfloat162float(__float2bfloat16_rn(p31));
            uint32_t ah[4], alo[4];
            ah[0]  = bf2_pack(h00, h01);
            ah[1]  = bf2_pack(h10, h11);
            ah[2]  = bf2_pack(h20, h21);
            ah[3]  = bf2_pack(h30, h31);
            alo[0] = bf2_pack(p00 - h00, p01 - h01);
            alo[1] = bf2_pack(p10 - h10, p11 - h11);
            alo[2] = bf2_pack(p20 - h20, p21 - h21);
            alo[3] = bf2_pack(p30 - h30, p31 - h31);

            #pragma unroll
            for (int nd2 = 0; nd2 < 4; nd2++) {
                uint32_t vh[4], vl[4];
                ldsm_x4_t(vh, sVa + ((kg * 16 + vrow) * KST + nd2 * 16 + vcoff) * 2);
                mma_bf16(oacc[2 * nd2],     ah,  vh[0], vh[1]);
                mma_bf16(oacc[2 * nd2 + 1], ah,  vh[2], vh[3]);
                mma_bf16(oacc[2 * nd2],     alo, vh[0], vh[1]);
                mma_bf16(oacc[2 * nd2 + 1], alo, vh[2], vh[3]);
                ldsm_x4_t(vl, sVa + ((kg * 16 + vrow) * KST + 64 + nd2 * 16 + vcoff) * 2);
                mma_bf16(oacc[2 * nd2],     ah,  vl[0], vl[1]);
                mma_bf16(oacc[2 * nd2 + 1], ah,  vl[2], vl[3]);
            }
        }
        __syncthreads();
    }

    // ---- normalize + write bf16 hi/lo into g_ab [4096, 2048]
    const float inv0 = 1.f / ls0, inv1 = 1.f / ls1;
    const int row0 = qt * 64 + w * 16 + (l >> 2);
    const size_t rbase0 = ((size_t)b * S_ + row0) * 2048;
    const size_t rbase1 = ((size_t)b * S_ + row0 + 8) * 2048;
    #pragma unroll
    for (int nd = 0; nd < 8; nd++) {
        int col = h * 64 + nd * 8 + 2 * (l & 3);
        float o00 = oacc[nd][0] * inv0, o01 = oacc[nd][1] * inv0;
        float o10 = oacc[nd][2] * inv1, o11 = oacc[nd][3] * inv1;
        float h00 = __bfloat162float(__float2bfloat16_rn(o00));
        float h01 = __bfloat162float(__float2bfloat16_rn(o01));
        float h10 = __bfloat162float(__float2bfloat16_rn(o10));
        float h11 = __bfloat162float(__float2bfloat16_rn(o11));
        *reinterpret_cast<uint32_t*>(&outb[rbase0 + col])        = bf2_pack(h00, h01);
        *reinterpret_cast<uint32_t*>(&outb[rbase0 + 1024 + col]) = bf2_pack(o00 - h00, o01 - h01);
        *reinterpret_cast<uint32_t*>(&outb[rbase1 + col])        = bf2_pack(h10, h11);
        *reinterpret_cast<uint32_t*>(&outb[rbase1 + 1024 + col]) = bf2_pack(o10 - h10, o11 - h11);
    }
}

// ---------------------------------------------------------------------------
extern "C" void kernel_launch(void* const* d_in, const int* in_sizes, int n_in,
                              void* d_out, int out_size)
{
    const float* x  = (const float*)d_in[0];
    const float* Wq = (const float*)d_in[1];
    const float* bq = (const float*)d_in[2];
    const float* Wk = (const float*)d_in[3];
    const float* bk = (const float*)d_in[4];
    const float* Wv = (const float*)d_in[5];
    const float* bv = (const float*)d_in[6];
    const float* Wo = (const float*)d_in[7];
    const float* bo = (const float*)d_in[8];

    __nv_bfloat16 *xb, *wqb, *wkb, *wvb, *wob, *ab, *qp, *kp, *vp;
    cudaGetSymbolAddress((void**)&xb,  g_xb);
    cudaGetSymbolAddress((void**)&wqb, g_wq);
    cudaGetSymbolAddress((void**)&wkb, g_wk);
    cudaGetSymbolAddress((void**)&wvb, g_wv);
    cudaGetSymbolAddress((void**)&wob, g_wo);
    cudaGetSymbolAddress((void**)&ab,  g_ab);
    cudaGetSymbolAddress((void**)&qp,  g_qb);
    cudaGetSymbolAddress((void**)&kp,  g_kb);
    cudaGetSymbolAddress((void**)&vp,  g_vb);

    const int SMEM_GEMM = 2 * SAB;   // 36864 B
    cudaFuncSetAttribute(hmma_gemm<0>, cudaFuncAttributeMaxDynamicSharedMemorySize, SMEM_GEMM);
    cudaFuncSetAttribute(hmma_gemm<1>, cudaFuncAttributeMaxDynamicSharedMemorySize, SMEM_GEMM);

    // pre-convert inputs to bf16 hi/lo
    convert_hl<<<MTOT, 256>>>(x, xb);
    convert_hl<<<E_, 256>>>(Wq, wqb);
    convert_hl<<<E_, 256>>>(Wk, wkb);
    convert_hl<<<E_, 256>>>(Wv, wvb);
    convert_hl<<<E_, 256>>>(Wo, wob);

    // fused Q/K/V projections (bf16 hi/lo out, Q pre-scaled by 1/8)
    dim3 qkv_grid(E_ / 128, MTOT / 128, 3);
    hmma_gemm<1><<<qkv_grid, 256, SMEM_GEMM>>>(xb, wqb, wkb, wvb, bq, bk, bv, qp, kp, vp);

    // tensor-core flash attention (writes bf16 hi/lo attn output)
    dim3 fgrid(S_ / 64, H_, B_);
    flash_tc<<<fgrid, 128>>>(ab);

    // output projection (fp32 out)
    dim3 o_grid(E_ / 128, MTOT / 128, 1);
    hmma_gemm<0><<<o_grid, 256, SMEM_GEMM>>>(ab, wob, wob, wob, bo, bo, bo,
                                             d_out, d_out, d_out);
}

// round 7
// speedup vs baseline: 1.3684x; 1.2528x over previous
#include <cuda_runtime.h>
#include <cuda_bf16.h>
#include <math.h>
#include <stdint.h>

#define B_   2
#define S_   2048
#define E_   1024
#define H_   16
#define D_   64
#define MTOT (B_*S_)   // 4096
#define QSZ_ ((size_t)B_*H_*S_*D_)   // 4194304

// Scratch (allocation-free rule: __device__ globals)
// bf16 hi/lo buffers. x/W/attn: [row][hi1024|lo1024]. q/k/v: hi block then lo block, [B,H,S,D].
__device__ __align__(16) __nv_bfloat16 g_xb[(size_t)MTOT*2048];
__device__ __align__(16) __nv_bfloat16 g_wq[(size_t)E_*2048];
__device__ __align__(16) __nv_bfloat16 g_wk[(size_t)E_*2048];
__device__ __align__(16) __nv_bfloat16 g_wv[(size_t)E_*2048];
__device__ __align__(16) __nv_bfloat16 g_wo[(size_t)E_*2048];
__device__ __align__(16) __nv_bfloat16 g_ab[(size_t)MTOT*2048];
__device__ __align__(16) __nv_bfloat16 g_qb[2*QSZ_];
__device__ __align__(16) __nv_bfloat16 g_kb[2*QSZ_];
__device__ __align__(16) __nv_bfloat16 g_vb[2*QSZ_];

// ---------------------------------------------------------------------------
// PTX helpers (baseline PTX, compiles on plain compute_103)
// ---------------------------------------------------------------------------
__device__ __forceinline__ uint32_t smem_u32(const void* p) {
    uint32_t a;
    asm("{ .reg .u64 t; cvta.to.shared.u64 t, %1; cvt.u32.u64 %0, t; }"
        : "=r"(a) : "l"(p));
    return a;
}
__device__ __forceinline__ void ldsm_x4(uint32_t r[4], uint32_t addr) {
    asm volatile("ldmatrix.sync.aligned.m8n8.x4.shared.b16 {%0,%1,%2,%3}, [%4];"
        : "=r"(r[0]), "=r"(r[1]), "=r"(r[2]), "=r"(r[3]) : "r"(addr));
}
__device__ __forceinline__ void ldsm_x4_t(uint32_t r[4], uint32_t addr) {
    asm volatile("ldmatrix.sync.aligned.m8n8.x4.trans.shared.b16 {%0,%1,%2,%3}, [%4];"
        : "=r"(r[0]), "=r"(r[1]), "=r"(r[2]), "=r"(r[3]) : "r"(addr));
}
__device__ __forceinline__ void mma_bf16(float c[4], const uint32_t a[4],
                                         uint32_t b0, uint32_t b1) {
    asm volatile("mma.sync.aligned.m16n8k16.row.col.f32.bf16.bf16.f32 "
        "{%0,%1,%2,%3}, {%4,%5,%6,%7}, {%8,%9}, {%0,%1,%2,%3};"
        : "+f"(c[0]), "+f"(c[1]), "+f"(c[2]), "+f"(c[3])
        : "r"(a[0]), "r"(a[1]), "r"(a[2]), "r"(a[3]), "r"(b0), "r"(b1));
}
__device__ __forceinline__ uint32_t bf2_pack(float x, float y) {
    __nv_bfloat162 h = __floats2bfloat162_rn(x, y);
    return *reinterpret_cast<uint32_t*>(&h);
}

// ---------------------------------------------------------------------------
// Pre-convert fp32 [nrows,1024] -> bf16 hi/lo [nrows,2048] ([hi1024|lo1024])
// ---------------------------------------------------------------------------
__device__ __forceinline__ void conv_body(const float* src, __nv_bfloat16* dst, int idx)
{
    int row = idx >> 8, c4 = idx & 255;
    float4 v = reinterpret_cast<const float4*>(src)[idx];
    float hx = __bfloat162float(__float2bfloat16_rn(v.x));
    float hy = __bfloat162float(__float2bfloat16_rn(v.y));
    float hz = __bfloat162float(__float2bfloat16_rn(v.z));
    float hw = __bfloat162float(__float2bfloat16_rn(v.w));
    uint2 hi = { bf2_pack(hx, hy), bf2_pack(hz, hw) };
    uint2 lo = { bf2_pack(v.x - hx, v.y - hy), bf2_pack(v.z - hz, v.w - hw) };
    *reinterpret_cast<uint2*>(&dst[(size_t)row * 2048 + c4 * 4])        = hi;
    *reinterpret_cast<uint2*>(&dst[(size_t)row * 2048 + 1024 + c4 * 4]) = lo;
}

__global__ __launch_bounds__(256)
void convert_x(const float* __restrict__ src, __nv_bfloat16* __restrict__ dst)
{
    conv_body(src, dst, blockIdx.x * 256 + threadIdx.x);
}

// all four weights in one launch: blockIdx.y selects
__global__ __launch_bounds__(256)
void convert_w4(const float* __restrict__ w0, const float* __restrict__ w1,
                const float* __restrict__ w2, const float* __restrict__ w3,
                __nv_bfloat16* __restrict__ d0, __nv_bfloat16* __restrict__ d1,
                __nv_bfloat16* __restrict__ d2, __nv_bfloat16* __restrict__ d3)
{
    int y = blockIdx.y;
    const float* src = (y == 0) ? w0 : (y == 1) ? w1 : (y == 2) ? w2 : w3;
    __nv_bfloat16* dst = (y == 0) ? d0 : (y == 1) ? d1 : (y == 2) ? d2 : d3;
    conv_body(src, dst, blockIdx.x * 256 + threadIdx.x);
}

// ---------------------------------------------------------------------------
// bf16x3 tensor-core GEMM, software-pipelined ping-pong smem (1 sync/iter):
//   C = (A * W^T + bias) [* scl]
// A: [M,2048] bf16 hi|lo.  W: [1024,2048] bf16 hi|lo.
// CTA tile 128x128, 256 threads (8 warps), warp tile 64x32 (4x4 m16n8k16).
// smem chunk: 128 rows x [hi32|lo32] bf16, stride 72. Two buffers per operand.
// 3-term: hi*hi + hi*lo + lo*hi.
// LAYOUT 0: fp32 out C[m*1024+n]
// LAYOUT 1: bf16 hi/lo out scattered [B,H,S,D]; z=0 (Q) scaled by 1/8
// ---------------------------------------------------------------------------
#define SAST 72             // smem row stride in bf16 (144 bytes)
#define SAB  (128*SAST*2)   // bytes per operand buffer: 18432

template<int LAYOUT>
__global__ __launch_bounds__(256, 2)
void hmma_gemm(const __nv_bfloat16* __restrict__ A,
               const __nv_bfloat16* __restrict__ W0,
               const __nv_bfloat16* __restrict__ W1,
               const __nv_bfloat16* __restrict__ W2,
               const float* __restrict__ b0p, const float* __restrict__ b1p,
               const float* __restrict__ b2p,
               void* __restrict__ C0v, void* __restrict__ C1v,
               void* __restrict__ C2v)
{
    extern __shared__ char smem[];
    const uint32_t base = smem_u32(smem);
    // layout: sA0 @0, sA1 @SAB, sB0 @2*SAB, sB1 @3*SAB

    const int z = blockIdx.z;
    const __nv_bfloat16* W = (z == 0) ? W0 : (z == 1) ? W1 : W2;
    const float* bias      = (z == 0) ? b0p : (z == 1) ? b1p : b2p;
    void*        Cv        = (z == 0) ? C0v : (z == 1) ? C1v : C2v;
    const float  scl       = (LAYOUT == 1 && z == 0) ? 0.125f : 1.0f;

    const int t  = threadIdx.x;
    const int w  = t >> 5;
    const int l  = t & 31;
    const int wy = w >> 2;           // 0..1
    const int wx = w & 3;            // 0..3
    const int m0 = blockIdx.y * 128;
    const int n0 = blockIdx.x * 128;

    float acc[4][4][4];
    #pragma unroll
    for (int i = 0; i < 4; i++)
        #pragma unroll
        for (int j = 0; j < 4; j++) {
            acc[i][j][0] = 0.f; acc[i][j][1] = 0.f;
            acc[i][j][2] = 0.f; acc[i][j][3] = 0.f;
        }

    const uint32_t a_row  = (uint32_t)(l & 15);
    const uint32_t a_koff = (l & 16) ? 8u : 0u;
    const uint32_t b_row  = (uint32_t)((l & 7) + ((l & 16) ? 8 : 0));
    const uint32_t b_koff = (l & 8) ? 8u : 0u;

    // per-thread staging: 4 uint4 per operand per chunk
    // idx = t + i*256; row = idx>>3 (0..127); c8 = idx&7
    // gmem col: c8*8 + (c8>=4 ? 992 : 0)   (lo half at +1024-32)
    uint4 va[4], vb[4];

    auto load_chunk = [&](int k0) {
        #pragma unroll
        for (int i = 0; i < 4; i++) {
            int idx = t + i * 256;
            int row = idx >> 3, c8 = idx & 7;
            int goff = k0 + c8 * 8 + ((c8 >= 4) ? 992 : 0);
            va[i] = *reinterpret_cast<const uint4*>(&A[(size_t)(m0 + row) * 2048 + goff]);
            vb[i] = *reinterpret_cast<const uint4*>(&W[(size_t)(n0 + row) * 2048 + goff]);
        }
    };
    auto store_chunk = [&](int sel) {
        const uint32_t dA = base + (uint32_t)sel * SAB;
        const uint32_t dB = base + 2 * SAB + (uint32_t)sel * SAB;
        #pragma unroll
        for (int i = 0; i < 4; i++) {
            int idx = t + i * 256;
            int row = idx >> 3, c8 = idx & 7;
            uint32_t off = (uint32_t)(row * SAST + c8 * 8) * 2;
            *reinterpret_cast<uint4*>(smem + (dA - base) + off) = va[i];
            *reinterpret_cast<uint4*>(smem + (dB - base) + off) = vb[i];
        }
    };
    auto mma_chunk = [&](int sel) {
        const uint32_t sA = base + (uint32_t)sel * SAB;
        const uint32_t sB = base + 2 * SAB + (uint32_t)sel * SAB;
        #pragma unroll
        for (int ka = 0; ka < 4; ka++) {
            uint32_t af[4][4];
            #pragma unroll
            for (int mi = 0; mi < 4; mi++) {
                uint32_t row = (uint32_t)(wy * 64 + mi * 16) + a_row;
                uint32_t col = (uint32_t)(ka * 16) + a_koff;
                ldsm_x4(af[mi], sA + row * (SAST * 2) + col * 2);
            }
            const int nkb  = (ka < 2) ? 2 : 1;
            const int kbl0 = (ka == 0) ? 0 : (ka == 1) ? 1 : (ka == 2) ? 0 : 1;
            const int kbl1 = (ka == 0) ? 2 : 3;
            #pragma unroll
            for (int j = 0; j < 2; j++) {
                if (j >= nkb) break;
                const int kb = (j == 0) ? kbl0 : kbl1;
                #pragma unroll
                for (int nb = 0; nb < 2; nb++) {
                    uint32_t bf[4];
                    uint32_t row = (uint32_t)(wx * 32 + nb * 16) + b_row;
                    uint32_t col = (uint32_t)(kb * 16) + b_koff;
                    ldsm_x4(bf, sB + row * (SAST * 2) + col * 2);
                    #pragma unroll
                    for (int mi = 0; mi < 4; mi++) {
                        mma_bf16(acc[mi][nb * 2 + 0], af[mi], bf[0], bf[1]);
                        mma_bf16(acc[mi][nb * 2 + 1], af[mi], bf[2], bf[3]);
                    }
                }
            }
        }
    };

    // ---- pipelined mainloop: 1 sync per iteration
    load_chunk(0);
    store_chunk(0);
    __syncthreads();
    for (int kc = 0; kc < 31; kc++) {
        load_chunk((kc + 1) * 32);     // independent: overlaps MMA below
        mma_chunk(kc & 1);
        store_chunk((kc + 1) & 1);     // other buffer — safe without extra sync
        __syncthreads();
    }
    mma_chunk(31 & 1);

    // ---- epilogue
    #pragma unroll
    for (int mi = 0; mi < 4; mi++) {
        #pragma unroll
        for (int ni = 0; ni < 4; ni++) {
            int n = n0 + wx * 32 + ni * 8 + 2 * (l & 3);
            float2 bv = *reinterpret_cast<const float2*>(&bias[n]);
            #pragma unroll
            for (int half = 0; half < 2; half++) {
                int m = m0 + wy * 64 + mi * 16 + (l >> 2) + half * 8;
                float vx = acc[mi][ni][half * 2 + 0] + bv.x;
                float vy = acc[mi][ni][half * 2 + 1] + bv.y;
                if (LAYOUT == 0) {
                    float* C = (float*)Cv;
                    float2 ov; ov.x = vx; ov.y = vy;
                    *reinterpret_cast<float2*>(&C[(size_t)m * E_ + n]) = ov;
                } else {
                    vx *= scl; vy *= scl;
                    __nv_bfloat16* Cb = (__nv_bfloat16*)Cv;
                    float hx = __bfloat162float(__float2bfloat16_rn(vx));
                    float hy = __bfloat162float(__float2bfloat16_rn(vy));
                    uint32_t hi2 = bf2_pack(hx, hy);
                    uint32_t lo2 = bf2_pack(vx - hx, vy - hy);
                    int bb = m >> 11, s = m & 2047;
                    int hh = n >> 6,  d = n & 63;
                    size_t idx = ((((size_t)bb * H_ + hh) * S_ + s) << 6) + d;
                    *reinterpret_cast<uint32_t*>(&Cb[idx])        = hi2;
                    *reinterpret_cast<uint32_t*>(&Cb[QSZ_ + idx]) = lo2;
                }
            }
        }
    }
}

// ---------------------------------------------------------------------------
// Tensor-core flash attention (bf16x3), ALiBi + causal (R4 structure)
// grid = (S/64, H, B), block = 128 (4 warps). Warp = 16 query rows.
// smem rows: [hi(64) | lo(64)] bf16, stride 136.
// Output: bf16 hi/lo into g_ab [4096, 2048].
// ---------------------------------------------------------------------------
#define KST 136

__global__ __launch_bounds__(128)
void flash_tc(__nv_bfloat16* __restrict__ outb)
{
    __shared__ __align__(16) __nv_bfloat16 sK[64 * KST];
    __shared__ __align__(16) __nv_bfloat16 sV[64 * KST];

    const int t = threadIdx.x;
    const int w = t >> 5, l = t & 31;
    const int qt = blockIdx.x, h = blockIdx.y, b = blockIdx.z;
    const size_t hd_base = ((size_t)b * H_ + h) * S_ * D_;

    const uint32_t sKa = smem_u32(sK);
    const uint32_t sVa = smem_u32(sV);

    const float slope = exp2f(-0.5f * (float)(h + 1));   // H=16 power of 2

    // ---- stage Q tile into sK, extract persistent A-fragments
    {
        const uint4* qh4 = reinterpret_cast<const uint4*>(g_qb + hd_base + (size_t)qt * 64 * 64);
        const uint4* ql4 = reinterpret_cast<const uint4*>(g_qb + QSZ_ + hd_base + (size_t)qt * 64 * 64);
        #pragma unroll
        for (int i = 0; i < 4; i++) {
            int idx = t + i * 128;   // 0..511
            int row = idx >> 3, c8 = idx & 7;
            *reinterpret_cast<uint4*>(&sK[row * KST + c8 * 8])      = qh4[idx];
            *reinterpret_cast<uint4*>(&sK[row * KST + 64 + c8 * 8]) = ql4[idx];
        }
    }
    __syncthreads();

    uint32_t qhf[4][4], qlf[4][4];
    {
        uint32_t arow = (uint32_t)(w * 16 + (l & 15));
        uint32_t acol = (l & 16) ? 8u : 0u;
        #pragma unroll
        for (int kg = 0; kg < 4; kg++) {
            ldsm_x4(qhf[kg], sKa + (arow * KST + kg * 16 + acol) * 2);
            ldsm_x4(qlf[kg], sKa + (arow * KST + 64 + kg * 16 + acol) * 2);
        }
    }
    __syncthreads();

    const uint32_t brow  = (uint32_t)((l & 7) + ((l & 16) ? 8 : 0));
    const uint32_t bkoff = (l & 8) ? 8u : 0u;
    const uint32_t vrow  = (uint32_t)(l & 15);
    const uint32_t vcoff = (l & 16) ? 8u : 0u;

    const int qi0 = qt * 64 + w * 16 + (l >> 2);
    const int qi1 = qi0 + 8;
    const float rowb0 = slope * (float)qi0;
    const float rowb1 = slope * (float)qi1;

    float oacc[8][4];
    #pragma unroll
    for (int i = 0; i < 8; i++) {
        oacc[i][0] = 0.f; oacc[i][1] = 0.f; oacc[i][2] = 0.f; oacc[i][3] = 0.f;
    }
    float mst0 = -1e30f, mst1 = -1e30f, ls0 = 0.f, ls1 = 0.f;

    for (int kt = 0; kt <= qt; kt++) {
        // ---- load K/V bf16 tiles (hi|lo)
        {
            const uint4* kh4 = reinterpret_cast<const uint4*>(g_kb + hd_base + (size_t)kt * 64 * 64);
            const uint4* kl4 = reinterpret_cast<const uint4*>(g_kb + QSZ_ + hd_base + (size_t)kt * 64 * 64);
            const uint4* vh4 = reinterpret_cast<const uint4*>(g_vb + hd_base + (size_t)kt * 64 * 64);
            const uint4* vl4 = reinterpret_cast<const uint4*>(g_vb + QSZ_ + hd_base + (size_t)kt * 64 * 64);
            #pragma unroll
            for (int i = 0; i < 4; i++) {
                int idx = t + i * 128;
                int row = idx >> 3, c8 = idx & 7;
                *reinterpret_cast<uint4*>(&sK[row * KST + c8 * 8])      = kh4[idx];
                *reinterpret_cast<uint4*>(&sK[row * KST + 64 + c8 * 8]) = kl4[idx];
                *reinterpret_cast<uint4*>(&sV[row * KST + c8 * 8])      = vh4[idx];
                *reinterpret_cast<uint4*>(&sV[row * KST + 64 + c8 * 8]) = vl4[idx];
            }
        }
        __syncthreads();

        // ---- S = Q K^T (3-term: QhKh + QlKh + QhKl)
        float sacc[8][4];
        #pragma unroll
        for (int i = 0; i < 8; i++) {
            sacc[i][0] = 0.f; sacc[i][1] = 0.f; sacc[i][2] = 0.f; sacc[i][3] = 0.f;
        }
        #pragma unroll
        for (int kg = 0; kg < 4; kg++) {
            #pragma unroll
            for (int nb2 = 0; nb2 < 4; nb2++) {
                uint32_t bh[4], bl[4];
                ldsm_x4(bh, sKa + ((nb2 * 16 + brow) * KST + kg * 16 + bkoff) * 2);
                mma_bf16(sacc[2 * nb2],     qhf[kg], bh[0], bh[1]);
                mma_bf16(sacc[2 * nb2 + 1], qhf[kg], bh[2], bh[3]);
                mma_bf16(sacc[2 * nb2],     qlf[kg], bh[0], bh[1]);
                mma_bf16(sacc[2 * nb2 + 1], qlf[kg], bh[2], bh[3]);
                ldsm_x4(bl, sKa + ((nb2 * 16 + brow) * KST + 64 + kg * 16 + bkoff) * 2);
                mma_bf16(sacc[2 * nb2],     qhf[kg], bl[0], bl[1]);
                mma_bf16(sacc[2 * nb2 + 1], qhf[kg], bl[2], bl[3]);
            }
        }

        // ---- ALiBi bias + causal mask + online softmax
        const int kjb = kt * 64 + 2 * (l & 3);
        float rm0 = -1e30f, rm1 = -1e30f;
        #pragma unroll
        for (int nb = 0; nb < 8; nb++) {
            int kj0 = kjb + nb * 8;
            float f0 = slope * (float)kj0;
            float f1 = f0 + slope;
            float v00 = sacc[nb][0] + f0 - rowb0;
            float v01 = sacc[nb][1] + f1 - rowb0;
            float v10 = sacc[nb][2] + f0 - rowb1;
            float v11 = sacc[nb][3] + f1 - rowb1;
            if (kt == qt) {
                if (kj0     > qi0) v00 = -1e30f;
                if (kj0 + 1 > qi0) v01 = -1e30f;
                if (kj0     > qi1) v10 = -1e30f;
                if (kj0 + 1 > qi1) v11 = -1e30f;
            }
            sacc[nb][0] = v00; sacc[nb][1] = v01;
            sacc[nb][2] = v10; sacc[nb][3] = v11;
            rm0 = fmaxf(rm0, fmaxf(v00, v01));
            rm1 = fmaxf(rm1, fmaxf(v10, v11));
        }
        rm0 = fmaxf(rm0, __shfl_xor_sync(0xffffffffu, rm0, 1));
        rm0 = fmaxf(rm0, __shfl_xor_sync(0xffffffffu, rm0, 2));
        rm1 = fmaxf(rm1, __shfl_xor_sync(0xffffffffu, rm1, 1));
        rm1 = fmaxf(rm1, __shfl_xor_sync(0xffffffffu, rm1, 2));

        float mn0 = fmaxf(mst0, rm0), mn1 = fmaxf(mst1, rm1);
        float al0 = __expf(mst0 - mn0), al1 = __expf(mst1 - mn1);
        mst0 = mn0; mst1 = mn1;

        float rs0 = 0.f, rs1 = 0.f;
        #pragma unroll
        for (int nb = 0; nb < 8; nb++) {
            float p00 = __expf(sacc[nb][0] - mn0);
            float p01 = __expf(sacc[nb][1] - mn0);
            float p10 = __expf(sacc[nb][2] - mn1);
            float p11 = __expf(sacc[nb][3] - mn1);
            sacc[nb][0] = p00; sacc[nb][1] = p01;
            sacc[nb][2] = p10; sacc[nb][3] = p11;
            rs0 += p00 + p01;
            rs1 += p10 + p11;
        }
        rs0 += __shfl_xor_sync(0xffffffffu, rs0, 1);
        rs0 += __shfl_xor_sync(0xffffffffu, rs0, 2);
        rs1 += __shfl_xor_sync(0xffffffffu, rs1, 1);
        rs1 += __shfl_xor_sync(0xffffffffu, rs1, 2);
        ls0 = ls0 * al0 + rs0;
        ls1 = ls1 * al1 + rs1;

        #pragma unroll
        for (int nd = 0; nd < 8; nd++) {
            oacc[nd][0] *= al0; oacc[nd][1] *= al0;
            oacc[nd][2] *= al1; oacc[nd][3] *= al1;
        }

        // ---- O += P V (3-term: PhVh + PlVh + PhVl); P frags from S C-frags
        #pragma unroll
        for (int kg = 0; kg < 4; kg++) {
            float p00 = sacc[2 * kg][0],     p01 = sacc[2 * kg][1];
            float p10 = sacc[2 * kg][2],     p11 = sacc[2 * kg][3];
            float p20 = sacc[2 * kg + 1][0], p21 = sacc[2 * kg + 1][1];
            float p30 = sacc[2 * kg + 1][2], p31 = sacc[2 * kg + 1][3];
            float h00 = __bfloat162float(__float2bfloat16_rn(p00));
            float h01 = __bfloat162float(__float2bfloat16_rn(p01));
            float h10 = __bfloat162float(__float2bfloat16_rn(p10));
            float h11 = __bfloat162float(__float2bfloat16_rn(p11));
            float h20 = __bfloat162float(__float2bfloat16_rn(p20));
            float h21 = __bfloat162float(__float2bfloat16_rn(p21));
            float h30 = __bfloat162float(__float2bfloat16_rn(p30));
            float h31 = __bfloat162float(__float2bfloat16_rn(p31));
            uint32_t ah[4], alo[4];
            ah[0]  = bf2_pack(h00, h01);
            ah[1]  = bf2_pack(h10, h11);
            ah[2]  = bf2_pack(h20, h21);
            ah[3]  = bf2_pack(h30, h31);
            alo[0] = bf2_pack(p00 - h00, p01 - h01);
            alo[1] = bf2_pack(p10 - h10, p11 - h11);
            alo[2] = bf2_pack(p20 - h20, p21 - h21);
            alo[3] = bf2_pack(p30 - h30, p31 - h31);

            #pragma unroll
            for (int nd2 = 0; nd2 < 4; nd2++) {
                uint32_t vh[4], vl[4];
                ldsm_x4_t(vh, sVa + ((kg * 16 + vrow) * KST + nd2 * 16 + vcoff) * 2);
                mma_bf16(oacc[2 * nd2],     ah,  vh[0], vh[1]);
                mma_bf16(oacc[2 * nd2 + 1], ah,  vh[2], vh[3]);
                mma_bf16(oacc[2 * nd2],     alo, vh[0], vh[1]);
                mma_bf16(oacc[2 * nd2 + 1], alo, vh[2], vh[3]);
                ldsm_x4_t(vl, sVa + ((kg * 16 + vrow) * KST + 64 + nd2 * 16 + vcoff) * 2);
                mma_bf16(oacc[2 * nd2],     ah,  vl[0], vl[1]);
                mma_bf16(oacc[2 * nd2 + 1], ah,  vl[2], vl[3]);
            }
        }
        __syncthreads();
    }

    // ---- normalize + write bf16 hi/lo into g_ab [4096, 2048]
    const float inv0 = 1.f / ls0, inv1 = 1.f / ls1;
    const int row0 = qt * 64 + w * 16 + (l >> 2);
    const size_t rbase0 = ((size_t)b * S_ + row0) * 2048;
    const size_t rbase1 = ((size_t)b * S_ + row0 + 8) * 2048;
    #pragma unroll
    for (int nd = 0; nd < 8; nd++) {
        int col = h * 64 + nd * 8 + 2 * (l & 3);
        float o00 = oacc[nd][0] * inv0, o01 = oacc[nd][1] * inv0;
        float o10 = oacc[nd][2] * inv1, o11 = oacc[nd][3] * inv1;
        float h00 = __bfloat162float(__float2bfloat16_rn(o00));
        float h01 = __bfloat162float(__float2bfloat16_rn(o01));
        float h10 = __bfloat162float(__float2bfloat16_rn(o10));
        float h11 = __bfloat162float(__float2bfloat16_rn(o11));
        *reinterpret_cast<uint32_t*>(&outb[rbase0 + col])        = bf2_pack(h00, h01);
        *reinterpret_cast<uint32_t*>(&outb[rbase0 + 1024 + col]) = bf2_pack(o00 - h00, o01 - h01);
        *reinterpret_cast<uint32_t*>(&outb[rbase1 + col])        = bf2_pack(h10, h11);
        *reinterpret_cast<uint32_t*>(&outb[rbase1 + 1024 + col]) = bf2_pack(o10 - h10, o11 - h11);
    }
}

// ---------------------------------------------------------------------------
extern "C" void kernel_launch(void* const* d_in, const int* in_sizes, int n_in,
                              void* d_out, int out_size)
{
    const float* x  = (const float*)d_in[0];
    const float* Wq = (const float*)d_in[1];
    const float* bq = (const float*)d_in[2];
    const float* Wk = (const float*)d_in[3];
    const float* bk = (const float*)d_in[4];
    const float* Wv = (const float*)d_in[5];
    const float* bv = (const float*)d_in[6];
    const float* Wo = (const float*)d_in[7];
    const float* bo = (const float*)d_in[8];

    __nv_bfloat16 *xb, *wqb, *wkb, *wvb, *wob, *ab, *qp, *kp, *vp;
    cudaGetSymbolAddress((void**)&xb,  g_xb);
    cudaGetSymbolAddress((void**)&wqb, g_wq);
    cudaGetSymbolAddress((void**)&wkb, g_wk);
    cudaGetSymbolAddress((void**)&wvb, g_wv);
    cudaGetSymbolAddress((void**)&wob, g_wo);
    cudaGetSymbolAddress((void**)&ab,  g_ab);
    cudaGetSymbolAddress((void**)&qp,  g_qb);
    cudaGetSymbolAddress((void**)&kp,  g_kb);
    cudaGetSymbolAddress((void**)&vp,  g_vb);

    const int SMEM_GEMM = 4 * SAB;   // 73728 B (ping-pong buffers)
    cudaFuncSetAttribute(hmma_gemm<0>, cudaFuncAttributeMaxDynamicSharedMemorySize, SMEM_GEMM);
    cudaFuncSetAttribute(hmma_gemm<1>, cudaFuncAttributeMaxDynamicSharedMemorySize, SMEM_GEMM);

    // pre-convert inputs to bf16 hi/lo (x one launch, all weights one launch)
    convert_x<<<MTOT, 256>>>(x, xb);
    dim3 wgrid(E_, 4);
    convert_w4<<<wgrid, 256>>>(Wq, Wk, Wv, Wo, wqb, wkb, wvb, wob);

    // fused Q/K/V projections (bf16 hi/lo out, Q pre-scaled by 1/8)
    dim3 qkv_grid(E_ / 128, MTOT / 128, 3);
    hmma_gemm<1><<<qkv_grid, 256, SMEM_GEMM>>>(xb, wqb, wkb, wvb, bq, bk, bv, qp, kp, vp);

    // tensor-core flash attention (writes bf16 hi/lo attn output)
    dim3 fgrid(S_ / 64, H_, B_);
    flash_tc<<<fgrid, 128>>>(ab);

    // output projection (fp32 out)
    dim3 o_grid(E_ / 128, MTOT / 128, 1);
    hmma_gemm<0><<<o_grid, 256, SMEM_GEMM>>>(ab, wob, wob, wob, bo, bo, bo,
                                             d_out, d_out, d_out);
}